// round 3
// baseline (speedup 1.0000x reference)
#include <cuda_runtime.h>
#include <math.h>

#define BB 16
#define PP 16384
#define MM 2048
#define D_Z 512
#define D_PHI 256
#define D_R 64
#define H1 96
#define H2 96

// scratch (no allocation allowed)
__device__ float g_A[BB * H1];
__device__ float g_Cp[PP * H1];

__device__ __forceinline__ float gelu_exact(float x) {
    return 0.5f * x * (1.0f + erff(x * 0.70710678118654752440f));
}

// ---------------------------------------------------------------------------
// Kernel A: A[b,j] = b1[j] + sum_k g_q[b,k] * W1[k,j]   (16 x 96, trivial)
// ---------------------------------------------------------------------------
__global__ void kA(const float* __restrict__ g_q,
                   const float* __restrict__ W1,
                   const float* __restrict__ b1) {
    int idx = blockIdx.x * blockDim.x + threadIdx.x;
    if (idx >= BB * H1) return;
    int b = idx / H1, j = idx % H1;
    float s = b1[j];
    const float* gq = g_q + b * D_Z;
    #pragma unroll 8
    for (int k = 0; k < D_Z; k++) s += gq[k] * W1[k * H1 + j];
    g_A[idx] = s;
}

// ---------------------------------------------------------------------------
// Kernel B: Cp[p,j] = sum_k' feat(p,k') * W1[512+k', j]
// feat(p, k'): k'<256 -> phi_i+phi_j ; <512 -> |phi_i-phi_j| ; <768 -> phi_i*phi_j
//              <832 -> relation[p, k'-768]
// pair_index dtype is detected on-device (int32 vs int64): for int64 data the
// odd 32-bit words (hi halves of values < 2^31) are all zero; for int32 data
// they are the j-indices and cannot all be zero over 64 random pairs.
// Tiling: 64 pairs/block, 256 threads, thread = (pg 0..31, jg 0..7),
// owns pairs {pg, pg+32} x 12 j outputs. K processed in 13 chunks of 64.
// ---------------------------------------------------------------------------
#define TPB 64
#define FS_STRIDE 68

__global__ void __launch_bounds__(256) kB(const float* __restrict__ Phi,
                                          const void* __restrict__ pair_index,
                                          const float* __restrict__ rel,
                                          const float* __restrict__ W1) {
    __shared__ float Fs[TPB * FS_STRIDE];   // feature chunk, padded
    __shared__ float Wc[64 * 96];           // weight chunk
    __shared__ int   pi_sh[TPB * 2];

    int tid = threadIdx.x;
    int p0 = blockIdx.x * TPB;

    // ---- dtype detection + index load (128 index values per block) ----
    {
        const int* p32 = (const int*)pair_index;
        int w = 0;
        if (tid < TPB * 2) w = p32[(size_t)p0 * 2 + tid];   // int32-layout read
        int any_odd = __syncthreads_or((tid & 1) ? w : 0);
        if (tid < TPB * 2) {
            int v;
            if (any_odd != 0) {
                v = w;                                       // int32 data
            } else {
                const long long* p64 = (const long long*)pair_index;
                v = (int)p64[(size_t)p0 * 2 + tid];          // int64 data
            }
            v = v < 0 ? 0 : (v >= MM ? MM - 1 : v);
            pi_sh[tid] = v;
        }
    }

    int jg = tid & 7;    // j group: columns jg*12 .. jg*12+11
    int pg = tid >> 3;   // 0..31

    float acc0[12], acc1[12];
    #pragma unroll
    for (int i = 0; i < 12; i++) { acc0[i] = 0.f; acc1[i] = 0.f; }

    for (int kc = 0; kc < 13; kc++) {
        int mode  = kc >> 2;          // 0:sum 1:absdiff 2:prod 3:relation
        int cbase = (kc & 3) * 64;
        __syncthreads();              // protect Fs/Wc from previous iter readers
        // build feature chunk
        for (int t = tid; t < TPB * 64; t += 256) {
            int pp = t >> 6, kk = t & 63;
            float f;
            if (mode == 3) {
                f = rel[(size_t)(p0 + pp) * D_R + kk];
            } else {
                int i0 = pi_sh[pp * 2];
                int j0 = pi_sh[pp * 2 + 1];
                float a = Phi[i0 * D_PHI + cbase + kk];
                float c = Phi[j0 * D_PHI + cbase + kk];
                f = (mode == 0) ? (a + c) : (mode == 1) ? fabsf(a - c) : (a * c);
            }
            Fs[pp * FS_STRIDE + kk] = f;
        }
        // load weight chunk rows 512 + kc*64 .. +63  (as float4)
        for (int t = tid; t < 64 * 24; t += 256) {
            int kk = t / 24, c4 = t % 24;
            ((float4*)Wc)[kk * 24 + c4] =
                ((const float4*)(W1 + (size_t)(D_Z + kc * 64 + kk) * H1))[c4];
        }
        __syncthreads();

        #pragma unroll 4
        for (int kk = 0; kk < 64; kk++) {
            float f0 = Fs[pg * FS_STRIDE + kk];
            float f1 = Fs[(pg + 32) * FS_STRIDE + kk];
            const float4* w = (const float4*)(Wc + kk * 96 + jg * 12);
            float4 a0 = w[0], a1 = w[1], a2 = w[2];
            acc0[0]  += f0 * a0.x; acc1[0]  += f1 * a0.x;
            acc0[1]  += f0 * a0.y; acc1[1]  += f1 * a0.y;
            acc0[2]  += f0 * a0.z; acc1[2]  += f1 * a0.z;
            acc0[3]  += f0 * a0.w; acc1[3]  += f1 * a0.w;
            acc0[4]  += f0 * a1.x; acc1[4]  += f1 * a1.x;
            acc0[5]  += f0 * a1.y; acc1[5]  += f1 * a1.y;
            acc0[6]  += f0 * a1.z; acc1[6]  += f1 * a1.z;
            acc0[7]  += f0 * a1.w; acc1[7]  += f1 * a1.w;
            acc0[8]  += f0 * a2.x; acc1[8]  += f1 * a2.x;
            acc0[9]  += f0 * a2.y; acc1[9]  += f1 * a2.y;
            acc0[10] += f0 * a2.z; acc1[10] += f1 * a2.z;
            acc0[11] += f0 * a2.w; acc1[11] += f1 * a2.w;
        }
    }

    float* o0 = g_Cp + (size_t)(p0 + pg) * H1 + jg * 12;
    float* o1 = g_Cp + (size_t)(p0 + pg + 32) * H1 + jg * 12;
    ((float4*)o0)[0] = make_float4(acc0[0], acc0[1], acc0[2], acc0[3]);
    ((float4*)o0)[1] = make_float4(acc0[4], acc0[5], acc0[6], acc0[7]);
    ((float4*)o0)[2] = make_float4(acc0[8], acc0[9], acc0[10], acc0[11]);
    ((float4*)o1)[0] = make_float4(acc1[0], acc1[1], acc1[2], acc1[3]);
    ((float4*)o1)[1] = make_float4(acc1[4], acc1[5], acc1[6], acc1[7]);
    ((float4*)o1)[2] = make_float4(acc1[8], acc1[9], acc1[10], acc1[11]);
}

// ---------------------------------------------------------------------------
// Kernel C: out[b,p] = gelu(gelu(A[b]+Cp[p]) @ W2 + b2) @ W3 + b3
// Block: 8 pairs x 16 b = 128 rows, one thread per row.
// 96 accumulators (h2 pre-activation) in REGISTERS; stream k over h1:
//   v = gelu(A[b,k] + Cp[p,k]);  s[j] += v * W2[k,j]  (W2 row broadcast from smem)
// Static smem: 36864 (W2) + 6208 (A pad97) + 3104 (Cp pad97) + 768 = 46.9 KB
// ---------------------------------------------------------------------------
#define CPAIRS 8

__global__ void __launch_bounds__(128) kC(const float* __restrict__ W2,
                                          const float* __restrict__ b2,
                                          const float* __restrict__ W3,
                                          const float* __restrict__ b3,
                                          float* __restrict__ out) {
    __shared__ float W2sh[96 * 96];
    __shared__ float Ash[16 * 97];
    __shared__ float Cpsh[CPAIRS * 97];
    __shared__ float W3sh[96];
    __shared__ float b2sh[96];

    int tid = threadIdx.x;
    int p0 = blockIdx.x * CPAIRS;

    for (int t = tid; t < 2304; t += 128)
        ((float4*)W2sh)[t] = ((const float4*)W2)[t];
    for (int t = tid; t < BB * H1; t += 128) {
        int b = t / 96, k = t - b * 96;
        Ash[b * 97 + k] = g_A[t];
    }
    for (int t = tid; t < CPAIRS * H1; t += 128) {
        int pl = t / 96, k = t - pl * 96;
        Cpsh[pl * 97 + k] = g_Cp[(size_t)p0 * H1 + t];
    }
    if (tid < 96) { W3sh[tid] = W3[tid]; b2sh[tid] = b2[tid]; }
    __syncthreads();

    int b  = tid >> 3;   // 0..15
    int pl = tid & 7;    // 0..7
    const float* Ar = Ash + b * 97;
    const float* Cr = Cpsh + pl * 97;

    float s[96];
    #pragma unroll
    for (int j = 0; j < 96; j++) s[j] = b2sh[j];

    #pragma unroll 2
    for (int k = 0; k < 96; k++) {
        float v = gelu_exact(Ar[k] + Cr[k]);
        const float4* w = (const float4*)(W2sh + k * 96);
        #pragma unroll
        for (int j4 = 0; j4 < 24; j4++) {
            float4 a = w[j4];
            s[j4 * 4 + 0] += v * a.x;
            s[j4 * 4 + 1] += v * a.y;
            s[j4 * 4 + 2] += v * a.z;
            s[j4 * 4 + 3] += v * a.w;
        }
    }

    float acc = b3[0];
    #pragma unroll
    for (int j = 0; j < 96; j++) acc += gelu_exact(s[j]) * W3sh[j];

    out[(size_t)b * PP + p0 + pl] = acc;
}

// ---------------------------------------------------------------------------
extern "C" void kernel_launch(void* const* d_in, const int* in_sizes, int n_in,
                              void* d_out, int out_size) {
    const float* g_q = (const float*)d_in[0];
    const float* Phi = (const float*)d_in[1];
    const void*  pin = (const void*)d_in[2];
    const float* rel = (const float*)d_in[3];
    const float* W1  = (const float*)d_in[4];
    const float* b1  = (const float*)d_in[5];
    const float* W2  = (const float*)d_in[6];
    const float* b2  = (const float*)d_in[7];
    const float* W3  = (const float*)d_in[8];
    const float* b3  = (const float*)d_in[9];
    float* out = (float*)d_out;

    kA<<<(BB * H1 + 255) / 256, 256>>>(g_q, W1, b1);
    kB<<<PP / TPB, 256>>>(Phi, pin, rel, W1);
    kC<<<PP / CPAIRS, 128>>>(W2, b2, W3, b3, out);
}

// round 4
// speedup vs baseline: 1.0010x; 1.0010x over previous
#include <cuda_runtime.h>
#include <math.h>

#define BB 16
#define PP 16384
#define MM 2048
#define D_Z 512
#define D_PHI 256
#define D_R 64
#define H1 96
#define H2 96

// scratch (no allocation allowed)
__device__ float g_A[BB * H1];
__device__ float g_Cp[PP * H1];

__device__ __forceinline__ float gelu_exact(float x) {
    return 0.5f * x * (1.0f + erff(x * 0.70710678118654752440f));
}

// ---------------------------------------------------------------------------
// Kernel A: A[b,j] = b1[j] + sum_k g_q[b,k] * W1[k,j]   (16 x 96, trivial)
// ---------------------------------------------------------------------------
__global__ void kA(const float* __restrict__ g_q,
                   const float* __restrict__ W1,
                   const float* __restrict__ b1) {
    int idx = blockIdx.x * blockDim.x + threadIdx.x;
    if (idx >= BB * H1) return;
    int b = idx / H1, j = idx % H1;
    float s = b1[j];
    const float* gq = g_q + b * D_Z;
    #pragma unroll 8
    for (int k = 0; k < D_Z; k++) s += gq[k] * W1[k * H1 + j];
    g_A[idx] = s;
}

// ---------------------------------------------------------------------------
// Kernel B: Cp[p,j] = sum_k' feat(p,k') * W1[512+k', j]
// feat(p, k'): k'<256 -> phi_i+phi_j ; <512 -> |phi_i-phi_j| ; <768 -> phi_i*phi_j
//              <832 -> relation[p, k'-768]
// pair_index dtype is detected on-device (int32 vs int64): for int64 data the
// odd 32-bit words (hi halves of values < 2^31) are all zero; for int32 data
// they are the j-indices and cannot all be zero over 64 random pairs.
// Tiling: 64 pairs/block, 256 threads, thread = (pg 0..31, jg 0..7),
// owns pairs {pg, pg+32} x 12 j outputs. K processed in 13 chunks of 64.
// ---------------------------------------------------------------------------
#define TPB 64
#define FS_STRIDE 68

__global__ void __launch_bounds__(256) kB(const float* __restrict__ Phi,
                                          const void* __restrict__ pair_index,
                                          const float* __restrict__ rel,
                                          const float* __restrict__ W1) {
    __shared__ float Fs[TPB * FS_STRIDE];   // feature chunk, padded
    __shared__ float Wc[64 * 96];           // weight chunk
    __shared__ int   pi_sh[TPB * 2];

    int tid = threadIdx.x;
    int p0 = blockIdx.x * TPB;

    // ---- dtype detection + index load (128 index values per block) ----
    {
        const int* p32 = (const int*)pair_index;
        int w = 0;
        if (tid < TPB * 2) w = p32[(size_t)p0 * 2 + tid];   // int32-layout read
        int any_odd = __syncthreads_or((tid & 1) ? w : 0);
        if (tid < TPB * 2) {
            int v;
            if (any_odd != 0) {
                v = w;                                       // int32 data
            } else {
                const long long* p64 = (const long long*)pair_index;
                v = (int)p64[(size_t)p0 * 2 + tid];          // int64 data
            }
            v = v < 0 ? 0 : (v >= MM ? MM - 1 : v);
            pi_sh[tid] = v;
        }
    }

    int jg = tid & 7;    // j group: columns jg*12 .. jg*12+11
    int pg = tid >> 3;   // 0..31

    float acc0[12], acc1[12];
    #pragma unroll
    for (int i = 0; i < 12; i++) { acc0[i] = 0.f; acc1[i] = 0.f; }

    for (int kc = 0; kc < 13; kc++) {
        int mode  = kc >> 2;          // 0:sum 1:absdiff 2:prod 3:relation
        int cbase = (kc & 3) * 64;
        __syncthreads();              // protect Fs/Wc from previous iter readers
        // build feature chunk
        for (int t = tid; t < TPB * 64; t += 256) {
            int pp = t >> 6, kk = t & 63;
            float f;
            if (mode == 3) {
                f = rel[(size_t)(p0 + pp) * D_R + kk];
            } else {
                int i0 = pi_sh[pp * 2];
                int j0 = pi_sh[pp * 2 + 1];
                float a = Phi[i0 * D_PHI + cbase + kk];
                float c = Phi[j0 * D_PHI + cbase + kk];
                f = (mode == 0) ? (a + c) : (mode == 1) ? fabsf(a - c) : (a * c);
            }
            Fs[pp * FS_STRIDE + kk] = f;
        }
        // load weight chunk rows 512 + kc*64 .. +63  (as float4)
        for (int t = tid; t < 64 * 24; t += 256) {
            int kk = t / 24, c4 = t % 24;
            ((float4*)Wc)[kk * 24 + c4] =
                ((const float4*)(W1 + (size_t)(D_Z + kc * 64 + kk) * H1))[c4];
        }
        __syncthreads();

        #pragma unroll 4
        for (int kk = 0; kk < 64; kk++) {
            float f0 = Fs[pg * FS_STRIDE + kk];
            float f1 = Fs[(pg + 32) * FS_STRIDE + kk];
            const float4* w = (const float4*)(Wc + kk * 96 + jg * 12);
            float4 a0 = w[0], a1 = w[1], a2 = w[2];
            acc0[0]  += f0 * a0.x; acc1[0]  += f1 * a0.x;
            acc0[1]  += f0 * a0.y; acc1[1]  += f1 * a0.y;
            acc0[2]  += f0 * a0.z; acc1[2]  += f1 * a0.z;
            acc0[3]  += f0 * a0.w; acc1[3]  += f1 * a0.w;
            acc0[4]  += f0 * a1.x; acc1[4]  += f1 * a1.x;
            acc0[5]  += f0 * a1.y; acc1[5]  += f1 * a1.y;
            acc0[6]  += f0 * a1.z; acc1[6]  += f1 * a1.z;
            acc0[7]  += f0 * a1.w; acc1[7]  += f1 * a1.w;
            acc0[8]  += f0 * a2.x; acc1[8]  += f1 * a2.x;
            acc0[9]  += f0 * a2.y; acc1[9]  += f1 * a2.y;
            acc0[10] += f0 * a2.z; acc1[10] += f1 * a2.z;
            acc0[11] += f0 * a2.w; acc1[11] += f1 * a2.w;
        }
    }

    float* o0 = g_Cp + (size_t)(p0 + pg) * H1 + jg * 12;
    float* o1 = g_Cp + (size_t)(p0 + pg + 32) * H1 + jg * 12;
    ((float4*)o0)[0] = make_float4(acc0[0], acc0[1], acc0[2], acc0[3]);
    ((float4*)o0)[1] = make_float4(acc0[4], acc0[5], acc0[6], acc0[7]);
    ((float4*)o0)[2] = make_float4(acc0[8], acc0[9], acc0[10], acc0[11]);
    ((float4*)o1)[0] = make_float4(acc1[0], acc1[1], acc1[2], acc1[3]);
    ((float4*)o1)[1] = make_float4(acc1[4], acc1[5], acc1[6], acc1[7]);
    ((float4*)o1)[2] = make_float4(acc1[8], acc1[9], acc1[10], acc1[11]);
}

// ---------------------------------------------------------------------------
// Kernel C: out[b,p] = gelu(gelu(A[b]+Cp[p]) @ W2 + b2) @ W3 + b3
// Block: 8 pairs x 16 b = 128 rows, one thread per row.
// 96 accumulators (h2 pre-activation) in REGISTERS; stream k over h1:
//   v = gelu(A[b,k] + Cp[p,k]);  s[j] += v * W2[k,j]  (W2 row broadcast from smem)
// Static smem: 36864 (W2) + 6208 (A pad97) + 3104 (Cp pad97) + 768 = 46.9 KB
// ---------------------------------------------------------------------------
#define CPAIRS 8

__global__ void __launch_bounds__(128) kC(const float* __restrict__ W2,
                                          const float* __restrict__ b2,
                                          const float* __restrict__ W3,
                                          const float* __restrict__ b3,
                                          float* __restrict__ out) {
    __shared__ float W2sh[96 * 96];
    __shared__ float Ash[16 * 97];
    __shared__ float Cpsh[CPAIRS * 97];
    __shared__ float W3sh[96];
    __shared__ float b2sh[96];

    int tid = threadIdx.x;
    int p0 = blockIdx.x * CPAIRS;

    for (int t = tid; t < 2304; t += 128)
        ((float4*)W2sh)[t] = ((const float4*)W2)[t];
    for (int t = tid; t < BB * H1; t += 128) {
        int b = t / 96, k = t - b * 96;
        Ash[b * 97 + k] = g_A[t];
    }
    for (int t = tid; t < CPAIRS * H1; t += 128) {
        int pl = t / 96, k = t - pl * 96;
        Cpsh[pl * 97 + k] = g_Cp[(size_t)p0 * H1 + t];
    }
    if (tid < 96) { W3sh[tid] = W3[tid]; b2sh[tid] = b2[tid]; }
    __syncthreads();

    int b  = tid >> 3;   // 0..15
    int pl = tid & 7;    // 0..7
    const float* Ar = Ash + b * 97;
    const float* Cr = Cpsh + pl * 97;

    float s[96];
    #pragma unroll
    for (int j = 0; j < 96; j++) s[j] = b2sh[j];

    #pragma unroll 2
    for (int k = 0; k < 96; k++) {
        float v = gelu_exact(Ar[k] + Cr[k]);
        const float4* w = (const float4*)(W2sh + k * 96);
        #pragma unroll
        for (int j4 = 0; j4 < 24; j4++) {
            float4 a = w[j4];
            s[j4 * 4 + 0] += v * a.x;
            s[j4 * 4 + 1] += v * a.y;
            s[j4 * 4 + 2] += v * a.z;
            s[j4 * 4 + 3] += v * a.w;
        }
    }

    float acc = b3[0];
    #pragma unroll
    for (int j = 0; j < 96; j++) acc += gelu_exact(s[j]) * W3sh[j];

    out[(size_t)b * PP + p0 + pl] = acc;
}

// ---------------------------------------------------------------------------
extern "C" void kernel_launch(void* const* d_in, const int* in_sizes, int n_in,
                              void* d_out, int out_size) {
    const float* g_q = (const float*)d_in[0];
    const float* Phi = (const float*)d_in[1];
    const void*  pin = (const void*)d_in[2];
    const float* rel = (const float*)d_in[3];
    const float* W1  = (const float*)d_in[4];
    const float* b1  = (const float*)d_in[5];
    const float* W2  = (const float*)d_in[6];
    const float* b2  = (const float*)d_in[7];
    const float* W3  = (const float*)d_in[8];
    const float* b3  = (const float*)d_in[9];
    float* out = (float*)d_out;

    kA<<<(BB * H1 + 255) / 256, 256>>>(g_q, W1, b1);
    kB<<<PP / TPB, 256>>>(Phi, pin, rel, W1);
    kC<<<PP / CPAIRS, 128>>>(W2, b2, W3, b3, out);
}